// round 12
// baseline (speedup 1.0000x reference)
#include <cuda_runtime.h>
#include <cuda_bf16.h>
#include <cstdint>

#define NN 100000
#define NE 600000
#define NV 50000
#define DIM 128
#define NNZ (NE + NN)
#define CHUNK ((NN + 1023) / 1024)   // 98

#define TILES1 ((NV + 63) / 64)     // 782
#define TILES2 ((NN + 63) / 64)     // 1563

// ---------------- scratch (static device globals; no allocation) ----------
__device__ int   g_deg[NN];
__device__ int   g_rowptr[NN + 1];
__device__ int   g_cursor[NN];
__device__ int   g_col[NNZ];
__device__ float g_dinv[NN];
__device__ int2  g_m1[NNZ];                  // layer-1 edge meta {x[col], dinv[col]}
__device__ int2  g_m2[NNZ];                  // layer-2 edge meta {col,    dinv[col]}
// W fragments, interleaved hi/lo: [layer][nt(16)][kt(8)][lane(32)] uint4
__device__ uint4 g_Wf[2 * 16 * 8 * 32];      // 128 KB total
__device__ float g_embW[(size_t)NV * DIM];   // emb @ W1
__device__ float g_agg [(size_t)NN * DIM];   // layer-1 output h1
__device__ float g_hw  [(size_t)NN * DIM];   // layer-2 pre-agg

// ---------------- degree / CSR build ---------------------------------------
__global__ void k_init_deg() {
    int i = blockIdx.x * blockDim.x + threadIdx.x;
    if (i < NN) g_deg[i] = 1;                // self-loop
}
__global__ void k_count_deg(const int* __restrict__ dst) {
    int e = blockIdx.x * blockDim.x + threadIdx.x;
    if (e < NE) atomicAdd(&g_deg[dst[e]], 1);
}
// Single-block exclusive scan of g_deg -> g_rowptr ONLY (grid-parallel work
// stays in k_fill_init; fusing rsqrt here serialized 100k MUFU on one SM).
__global__ __launch_bounds__(1024) void k_scan_fused() {
    __shared__ int s[1024];
    int tid = threadIdx.x;
    int lo = tid * CHUNK;
    int hi = lo + CHUNK; if (hi > NN) hi = NN;
    int sum = 0;
    #pragma unroll 4
    for (int i = lo; i < hi; i++) sum += g_deg[i];
    s[tid] = sum;
    __syncthreads();
    #pragma unroll
    for (int off = 1; off < 1024; off <<= 1) {
        int t = (tid >= off) ? s[tid - off] : 0;
        __syncthreads();
        s[tid] += t;
        __syncthreads();
    }
    int run = (tid == 0) ? 0 : s[tid - 1];
    #pragma unroll 4
    for (int i = lo; i < hi; i++) { g_rowptr[i] = run; run += g_deg[i]; }
    if (tid == 1023) g_rowptr[NN] = run;
}
__global__ void k_fill_init() {
    int i = blockIdx.x * blockDim.x + threadIdx.x;
    if (i < NN) {
        int base = g_rowptr[i];
        g_col[base] = i;                     // self-loop entry first
        g_cursor[i] = base + 1;
        g_dinv[i] = rsqrtf((float)g_deg[i]);
    }
}
__global__ void k_fill_edges(const int* __restrict__ src, const int* __restrict__ dst) {
    int e = blockIdx.x * blockDim.x + threadIdx.x;
    if (e < NE) {
        int pos = atomicAdd(&g_cursor[dst[e]], 1);
        g_col[pos] = src[e];
    }
}
// Edge-parallel meta pack: collapses spmm's col->dinv/x chain into one int2.
__global__ void k_prep_meta(const int* __restrict__ x) {
    int k = blockIdx.x * blockDim.x + threadIdx.x;
    if (k < NNZ) {
        int c = g_col[k];
        int w = __float_as_int(g_dinv[c]);
        g_m2[k] = make_int2(c, w);
        g_m1[k] = make_int2(x[c], w);
    }
}

// ---------------- helpers ---------------------------------------------------
__device__ __forceinline__ uint32_t pack_bf16(float lo_val, float hi_val) {
    uint32_t d;
    asm("cvt.rn.bf16x2.f32 %0, %1, %2;" : "=r"(d) : "f"(hi_val), "f"(lo_val));
    return d;
}
__device__ __forceinline__ float bf16lo_to_f32(uint32_t p) { return __uint_as_float(p << 16); }
__device__ __forceinline__ float bf16hi_to_f32(uint32_t p) { return __uint_as_float(p & 0xFFFF0000u); }

__device__ __forceinline__ void mma_bf16(float* c, const uint32_t* a, uint32_t b0, uint32_t b1) {
    asm volatile(
        "mma.sync.aligned.m16n8k16.row.col.f32.bf16.bf16.f32 "
        "{%0,%1,%2,%3}, {%4,%5,%6,%7}, {%8,%9}, {%0,%1,%2,%3};"
        : "+f"(c[0]), "+f"(c[1]), "+f"(c[2]), "+f"(c[3])
        : "r"(a[0]), "r"(a[1]), "r"(a[2]), "r"(a[3]), "r"(b0), "r"(b1));
}

// ---- W fragment prep: B frag (m16n8k16 col) for C = A @ W, hi/lo packed ---
__global__ void k_prep_wf(const float* __restrict__ W1, const float* __restrict__ W2) {
    int gid = blockIdx.x * blockDim.x + threadIdx.x;   // 8192 total
    if (gid >= 2 * 16 * 8 * 32) return;
    int lane  = gid & 31;
    int kt    = (gid >> 5) & 7;
    int nt    = (gid >> 8) & 15;
    int layer = gid >> 12;
    const float* W = layer ? W2 : W1;
    int n  = nt * 8 + (lane >> 2);
    int k0 = kt * 16 + (lane & 3) * 2;

    float v[4];
    v[0] = W[(k0    ) * DIM + n];
    v[1] = W[(k0 + 1) * DIM + n];
    v[2] = W[(k0 + 8) * DIM + n];
    v[3] = W[(k0 + 9) * DIM + n];
    float h[4], l[4];
    #pragma unroll
    for (int j = 0; j < 4; j++) {
        __nv_bfloat16 hb = __float2bfloat16_rn(v[j]);
        h[j] = __bfloat162float(hb);
        l[j] = v[j] - h[j];
    }
    g_Wf[gid] = make_uint4(pack_bf16(h[0], h[1]), pack_bf16(h[2], h[3]),
                           pack_bf16(l[0], l[1]), pack_bf16(l[2], l[3]));
}

// ---------------- GEMM via mma.sync bf16 split (3-pass) --------------------
// Exact R7/R11 kernel (best) + __ldcs on the read-once A stream.
#define SA_STRIDE 68
#define SMEM_GEMM (2 * 64 * SA_STRIDE * 4)    // 34816 B

__global__ __launch_bounds__(256, 3) void k_gemm_mma(
    const float* __restrict__ A, const uint4* __restrict__ Wf,
    float* __restrict__ C, int M)
{
    extern __shared__ uint32_t sAu[];
    uint32_t* sAh = sAu;                      // [64][SA_STRIDE]
    uint32_t* sAl = sAu + 64 * SA_STRIDE;
    int tid = threadIdx.x;
    int wid = tid >> 5;
    int lane = tid & 31;
    int row0 = blockIdx.x * 64;
    int rows_left = M - row0;

    {
        const float4* Av = (const float4*)(A + (size_t)row0 * DIM);
        #pragma unroll
        for (int i = 0; i < 8; i++) {
            int idx = tid + i * 256;
            int r = idx >> 5, c4 = idx & 31;
            float4 v = make_float4(0.f, 0.f, 0.f, 0.f);
            if (r < rows_left) v = __ldcs(Av + idx);   // read-once stream
            uint32_t h0 = pack_bf16(v.x, v.y);
            uint32_t h1 = pack_bf16(v.z, v.w);
            uint32_t l0 = pack_bf16(v.x - bf16lo_to_f32(h0), v.y - bf16hi_to_f32(h0));
            uint32_t l1 = pack_bf16(v.z - bf16lo_to_f32(h1), v.w - bf16hi_to_f32(h1));
            *(uint2*)&sAh[r * SA_STRIDE + c4 * 2] = make_uint2(h0, h1);
            *(uint2*)&sAl[r * SA_STRIDE + c4 * 2] = make_uint2(l0, l1);
        }
    }
    __syncthreads();

    int wr = wid >> 2;                 // row group 0..1 (32 rows)
    int wc = wid & 3;                  // col group 0..3 (4 nt = 32 cols)
    int q  = lane >> 2;                // row-in-group 0..7
    int w  = lane & 3;                 // k-pair slot 0..3

    float acc[2][4][4];
    #pragma unroll
    for (int m = 0; m < 2; m++)
        #pragma unroll
        for (int j = 0; j < 4; j++)
            acc[m][j][0] = acc[m][j][1] = acc[m][j][2] = acc[m][j][3] = 0.f;

    int rA = (wr * 32 + q) * SA_STRIDE;
    const uint4* pb0 = Wf + wc * 1024 + lane;

    #pragma unroll
    for (int kt = 0; kt < 8; kt++) {
        int kp = kt * 8 + w;
        uint32_t ah0[4], al0[4], ah1[4], al1[4];
        ah0[0] = sAh[rA + kp];                    ah0[1] = sAh[rA + 8  * SA_STRIDE + kp];
        ah0[2] = sAh[rA + kp + 4];                ah0[3] = sAh[rA + 8  * SA_STRIDE + kp + 4];
        ah1[0] = sAh[rA + 16 * SA_STRIDE + kp];   ah1[1] = sAh[rA + 24 * SA_STRIDE + kp];
        ah1[2] = sAh[rA + 16 * SA_STRIDE + kp+4]; ah1[3] = sAh[rA + 24 * SA_STRIDE + kp + 4];
        al0[0] = sAl[rA + kp];                    al0[1] = sAl[rA + 8  * SA_STRIDE + kp];
        al0[2] = sAl[rA + kp + 4];                al0[3] = sAl[rA + 8  * SA_STRIDE + kp + 4];
        al1[0] = sAl[rA + 16 * SA_STRIDE + kp];   al1[1] = sAl[rA + 24 * SA_STRIDE + kp];
        al1[2] = sAl[rA + 16 * SA_STRIDE + kp+4]; al1[3] = sAl[rA + 24 * SA_STRIDE + kp + 4];

        const uint4* pb = pb0 + kt * 32;
        uint4 b[4];
        #pragma unroll
        for (int j = 0; j < 4; j++)
            b[j] = __ldg(pb + j * 256);

        #pragma unroll
        for (int j = 0; j < 4; j++) {
            mma_bf16(acc[0][j], ah0, b[j].x, b[j].y);
            mma_bf16(acc[1][j], ah1, b[j].x, b[j].y);
        }
        #pragma unroll
        for (int j = 0; j < 4; j++) {
            mma_bf16(acc[0][j], al0, b[j].x, b[j].y);
            mma_bf16(acc[1][j], al1, b[j].x, b[j].y);
        }
        #pragma unroll
        for (int j = 0; j < 4; j++) {
            mma_bf16(acc[0][j], ah0, b[j].z, b[j].w);
            mma_bf16(acc[1][j], ah1, b[j].z, b[j].w);
        }
    }

    #pragma unroll
    for (int m = 0; m < 2; m++) {
        int rr0 = row0 + wr * 32 + m * 16 + q;
        int rr1 = rr0 + 8;
        #pragma unroll
        for (int j = 0; j < 4; j++) {
            int col = (wc * 4 + j) * 8 + w * 2;
            if (rr0 < M)
                *(float2*)&C[(size_t)rr0 * DIM + col] = make_float2(acc[m][j][0], acc[m][j][1]);
            if (rr1 < M)
                *(float2*)&C[(size_t)rr1 * DIM + col] = make_float2(acc[m][j][2], acc[m][j][3]);
        }
    }
}

// ---------------- SpMM gather with packed meta + software pipeline ---------
// One warp per node. Per edge: ONE int2 meta load + one feature-row load
// (chain depth 2); next group's meta prefetched under current feature loads.
__global__ __launch_bounds__(256) void k_spmm(
    const float* __restrict__ feat, const int2* __restrict__ meta,
    const float* __restrict__ bias, float* __restrict__ out)
{
    int node = (int)((blockIdx.x * blockDim.x + threadIdx.x) >> 5);
    if (node >= NN) return;
    int lane = threadIdx.x & 31;

    int start = g_rowptr[node];
    int end   = g_rowptr[node + 1];
    const float4* f4 = (const float4*)feat;

    float ax = 0.f, ay = 0.f, az = 0.f, aw = 0.f;
    int k = start;

    int2 m0, m1, m2, m3;
    bool have = (k + 3 < end);
    if (have) {
        m0 = meta[k]; m1 = meta[k + 1]; m2 = meta[k + 2]; m3 = meta[k + 3];
    }
    while (have) {
        int2 c0 = m0, c1 = m1, c2 = m2, c3 = m3;
        int kn = k + 4;
        bool haven = (kn + 3 < end);
        if (haven) {                       // prefetch next group under feat loads
            m0 = meta[kn]; m1 = meta[kn + 1]; m2 = meta[kn + 2]; m3 = meta[kn + 3];
        }
        float4 v0 = f4[(size_t)c0.x * 32 + lane];
        float4 v1 = f4[(size_t)c1.x * 32 + lane];
        float4 v2 = f4[(size_t)c2.x * 32 + lane];
        float4 v3 = f4[(size_t)c3.x * 32 + lane];
        float w0 = __int_as_float(c0.y), w1 = __int_as_float(c1.y);
        float w2 = __int_as_float(c2.y), w3 = __int_as_float(c3.y);
        ax = fmaf(w0, v0.x, ax); ay = fmaf(w0, v0.y, ay);
        az = fmaf(w0, v0.z, az); aw = fmaf(w0, v0.w, aw);
        ax = fmaf(w1, v1.x, ax); ay = fmaf(w1, v1.y, ay);
        az = fmaf(w1, v1.z, az); aw = fmaf(w1, v1.w, aw);
        ax = fmaf(w2, v2.x, ax); ay = fmaf(w2, v2.y, ay);
        az = fmaf(w2, v2.z, az); aw = fmaf(w2, v2.w, aw);
        ax = fmaf(w3, v3.x, ax); ay = fmaf(w3, v3.y, ay);
        az = fmaf(w3, v3.z, az); aw = fmaf(w3, v3.w, aw);
        k = kn;
        have = haven;
    }
    for (; k < end; k++) {
        int2 m = meta[k];
        float w = __int_as_float(m.y);
        float4 v = f4[(size_t)m.x * 32 + lane];
        ax = fmaf(w, v.x, ax); ay = fmaf(w, v.y, ay);
        az = fmaf(w, v.z, az); aw = fmaf(w, v.w, aw);
    }

    float di = g_dinv[node];
    float4 b = __ldg((const float4*)bias + lane);
    float4 o;
    o.x = fmaxf(fmaf(di, ax, b.x), 0.f);
    o.y = fmaxf(fmaf(di, ay, b.y), 0.f);
    o.z = fmaxf(fmaf(di, az, b.z), 0.f);
    o.w = fmaxf(fmaf(di, aw, b.w), 0.f);
    __stcs((float4*)out + (size_t)node * 32 + lane, o);   // streaming store
}

// ---------------- launch ----------------------------------------------------
extern "C" void kernel_launch(void* const* d_in, const int* in_sizes, int n_in,
                              void* d_out, int out_size) {
    const int*   x   = (const int*)d_in[0];
    const int*   src = (const int*)d_in[1];          // edge_index[0]
    const int*   dst = src + NE;                     // edge_index[1]
    const float* emb = (const float*)d_in[2];
    const float* W1  = (const float*)d_in[3];
    const float* b1  = (const float*)d_in[4];
    const float* W2  = (const float*)d_in[5];
    const float* b2  = (const float*)d_in[6];
    float*       out = (float*)d_out;

    float *p_embW, *p_agg, *p_hw;
    uint4 *p_Wf;
    int2 *p_m1, *p_m2;
    cudaGetSymbolAddress((void**)&p_embW, g_embW);
    cudaGetSymbolAddress((void**)&p_agg,  g_agg);
    cudaGetSymbolAddress((void**)&p_hw,   g_hw);
    cudaGetSymbolAddress((void**)&p_Wf,   g_Wf);
    cudaGetSymbolAddress((void**)&p_m1,   g_m1);
    cudaGetSymbolAddress((void**)&p_m2,   g_m2);

    cudaFuncSetAttribute(k_gemm_mma, cudaFuncAttributeMaxDynamicSharedMemorySize, SMEM_GEMM);

    // Launch order keeps GEMM1 as launch #4 (ncu profiles launch #4).
    k_init_deg  <<<(NN + 255) / 256, 256>>>();                       // 1
    k_count_deg <<<(NE + 255) / 256, 256>>>(dst);                    // 2
    k_prep_wf   <<<(2 * 16 * 8 * 32 + 255) / 256, 256>>>(W1, W2);    // 3
    k_gemm_mma  <<<TILES1, 256, SMEM_GEMM>>>(emb, p_Wf, p_embW, NV); // 4 <- profiled
    k_scan_fused<<<1, 1024>>>();                                     // 5
    k_fill_init <<<(NN + 255) / 256, 256>>>();                       // 6
    k_fill_edges<<<(NE + 255) / 256, 256>>>(src, dst);               // 7
    k_prep_meta <<<(NNZ + 255) / 256, 256>>>(x);                     // 8
    k_spmm      <<<(NN + 7) / 8, 256>>>(p_embW, p_m1, b1, p_agg);    // 9
    k_gemm_mma  <<<TILES2, 256, SMEM_GEMM>>>(p_agg, p_Wf + 16 * 8 * 32, p_hw, NN); // 10
    k_spmm      <<<(NN + 7) / 8, 256>>>(p_hw, p_m2, b2, out);        // 11
}

// round 13
// speedup vs baseline: 1.1203x; 1.1203x over previous
#include <cuda_runtime.h>
#include <cuda_bf16.h>
#include <cstdint>

#define NN 100000
#define NE 600000
#define NV 50000
#define DIM 128
#define NNZ (NE + NN)
#define CHUNK ((NN + 1023) / 1024)   // 98

#define TILES1 ((NV + 63) / 64)     // 782
#define TILES2 ((NN + 63) / 64)     // 1563

// ---------------- scratch (static device globals; no allocation) ----------
__device__ int   g_deg[NN];                  // EDGE degree only (self-loop folded later)
__device__ int   g_rowptr[NN + 1];
__device__ int   g_cursor[NN];
__device__ int   g_col[NNZ];
__device__ float g_dinv[NN];
// W fragments, interleaved hi/lo: [layer][nt(16)][kt(8)][lane(32)] uint4
__device__ uint4 g_Wf[2 * 16 * 8 * 32];      // 128 KB total
__device__ float g_embW[(size_t)NV * DIM];   // emb @ W1
__device__ float g_agg [(size_t)NN * DIM];   // layer-1 output h1
__device__ float g_hw  [(size_t)NN * DIM];   // layer-2 pre-agg

// ---------------- degree / CSR build ---------------------------------------
__global__ void k_count_deg(const int* __restrict__ dst) {
    int e = blockIdx.x * blockDim.x + threadIdx.x;
    if (e < NE) atomicAdd(&g_deg[dst[e]], 1);
}
// Single-block exclusive scan of (g_deg + 1) -> g_rowptr (self-loop folded).
// Grid-parallel work (rsqrt, col/cursor init) stays in k_fill_init.
__global__ __launch_bounds__(1024) void k_scan_fused() {
    __shared__ int s[1024];
    int tid = threadIdx.x;
    int lo = tid * CHUNK;
    int hi = lo + CHUNK; if (hi > NN) hi = NN;
    int sum = 0;
    #pragma unroll 4
    for (int i = lo; i < hi; i++) sum += g_deg[i] + 1;
    s[tid] = sum;
    __syncthreads();
    #pragma unroll
    for (int off = 1; off < 1024; off <<= 1) {
        int t = (tid >= off) ? s[tid - off] : 0;
        __syncthreads();
        s[tid] += t;
        __syncthreads();
    }
    int run = (tid == 0) ? 0 : s[tid - 1];
    #pragma unroll 4
    for (int i = lo; i < hi; i++) { g_rowptr[i] = run; run += g_deg[i] + 1; }
    if (tid == 1023) g_rowptr[NN] = run;
}
__global__ void k_fill_init() {
    int i = blockIdx.x * blockDim.x + threadIdx.x;
    if (i < NN) {
        int base = g_rowptr[i];
        g_col[base] = i;                     // self-loop entry first
        g_cursor[i] = base + 1;
        g_dinv[i] = rsqrtf((float)(g_deg[i] + 1));
    }
}
__global__ void k_fill_edges(const int* __restrict__ src, const int* __restrict__ dst) {
    int e = blockIdx.x * blockDim.x + threadIdx.x;
    if (e < NE) {
        int pos = atomicAdd(&g_cursor[dst[e]], 1);
        g_col[pos] = src[e];
    }
}

// ---------------- helpers ---------------------------------------------------
__device__ __forceinline__ uint32_t pack_bf16(float lo_val, float hi_val) {
    uint32_t d;
    asm("cvt.rn.bf16x2.f32 %0, %1, %2;" : "=r"(d) : "f"(hi_val), "f"(lo_val));
    return d;
}
__device__ __forceinline__ float bf16lo_to_f32(uint32_t p) { return __uint_as_float(p << 16); }
__device__ __forceinline__ float bf16hi_to_f32(uint32_t p) { return __uint_as_float(p & 0xFFFF0000u); }

__device__ __forceinline__ void mma_bf16(float* c, const uint32_t* a, uint32_t b0, uint32_t b1) {
    asm volatile(
        "mma.sync.aligned.m16n8k16.row.col.f32.bf16.bf16.f32 "
        "{%0,%1,%2,%3}, {%4,%5,%6,%7}, {%8,%9}, {%0,%1,%2,%3};"
        : "+f"(c[0]), "+f"(c[1]), "+f"(c[2]), "+f"(c[3])
        : "r"(a[0]), "r"(a[1]), "r"(a[2]), "r"(a[3]), "r"(b0), "r"(b1));
}

// ---- W fragment prep: B frag (m16n8k16 col) for C = A @ W, hi/lo packed ---
__global__ void k_prep_wf(const float* __restrict__ W1, const float* __restrict__ W2) {
    int gid = blockIdx.x * blockDim.x + threadIdx.x;   // 8192 total
    if (gid >= 2 * 16 * 8 * 32) return;
    int lane  = gid & 31;
    int kt    = (gid >> 5) & 7;
    int nt    = (gid >> 8) & 15;
    int layer = gid >> 12;
    const float* W = layer ? W2 : W1;
    int n  = nt * 8 + (lane >> 2);
    int k0 = kt * 16 + (lane & 3) * 2;

    float v[4];
    v[0] = W[(k0    ) * DIM + n];
    v[1] = W[(k0 + 1) * DIM + n];
    v[2] = W[(k0 + 8) * DIM + n];
    v[3] = W[(k0 + 9) * DIM + n];
    float h[4], l[4];
    #pragma unroll
    for (int j = 0; j < 4; j++) {
        __nv_bfloat16 hb = __float2bfloat16_rn(v[j]);
        h[j] = __bfloat162float(hb);
        l[j] = v[j] - h[j];
    }
    g_Wf[gid] = make_uint4(pack_bf16(h[0], h[1]), pack_bf16(h[2], h[3]),
                           pack_bf16(l[0], l[1]), pack_bf16(l[2], l[3]));
}

// ---------------- GEMM via mma.sync bf16 split (3-pass) --------------------
// Exact R7/R11 kernel (best) + __ldcs on the read-once A stream.
#define SA_STRIDE 68
#define SMEM_GEMM (2 * 64 * SA_STRIDE * 4)    // 34816 B

__global__ __launch_bounds__(256, 3) void k_gemm_mma(
    const float* __restrict__ A, const uint4* __restrict__ Wf,
    float* __restrict__ C, int M)
{
    extern __shared__ uint32_t sAu[];
    uint32_t* sAh = sAu;                      // [64][SA_STRIDE]
    uint32_t* sAl = sAu + 64 * SA_STRIDE;
    int tid = threadIdx.x;
    int wid = tid >> 5;
    int lane = tid & 31;
    int row0 = blockIdx.x * 64;
    int rows_left = M - row0;

    {
        const float4* Av = (const float4*)(A + (size_t)row0 * DIM);
        #pragma unroll
        for (int i = 0; i < 8; i++) {
            int idx = tid + i * 256;
            int r = idx >> 5, c4 = idx & 31;
            float4 v = make_float4(0.f, 0.f, 0.f, 0.f);
            if (r < rows_left) v = __ldcs(Av + idx);   // read-once stream
            uint32_t h0 = pack_bf16(v.x, v.y);
            uint32_t h1 = pack_bf16(v.z, v.w);
            uint32_t l0 = pack_bf16(v.x - bf16lo_to_f32(h0), v.y - bf16hi_to_f32(h0));
            uint32_t l1 = pack_bf16(v.z - bf16lo_to_f32(h1), v.w - bf16hi_to_f32(h1));
            *(uint2*)&sAh[r * SA_STRIDE + c4 * 2] = make_uint2(h0, h1);
            *(uint2*)&sAl[r * SA_STRIDE + c4 * 2] = make_uint2(l0, l1);
        }
    }
    __syncthreads();

    int wr = wid >> 2;                 // row group 0..1 (32 rows)
    int wc = wid & 3;                  // col group 0..3 (4 nt = 32 cols)
    int q  = lane >> 2;                // row-in-group 0..7
    int w  = lane & 3;                 // k-pair slot 0..3

    float acc[2][4][4];
    #pragma unroll
    for (int m = 0; m < 2; m++)
        #pragma unroll
        for (int j = 0; j < 4; j++)
            acc[m][j][0] = acc[m][j][1] = acc[m][j][2] = acc[m][j][3] = 0.f;

    int rA = (wr * 32 + q) * SA_STRIDE;
    const uint4* pb0 = Wf + wc * 1024 + lane;

    #pragma unroll
    for (int kt = 0; kt < 8; kt++) {
        int kp = kt * 8 + w;
        uint32_t ah0[4], al0[4], ah1[4], al1[4];
        ah0[0] = sAh[rA + kp];                    ah0[1] = sAh[rA + 8  * SA_STRIDE + kp];
        ah0[2] = sAh[rA + kp + 4];                ah0[3] = sAh[rA + 8  * SA_STRIDE + kp + 4];
        ah1[0] = sAh[rA + 16 * SA_STRIDE + kp];   ah1[1] = sAh[rA + 24 * SA_STRIDE + kp];
        ah1[2] = sAh[rA + 16 * SA_STRIDE + kp+4]; ah1[3] = sAh[rA + 24 * SA_STRIDE + kp + 4];
        al0[0] = sAl[rA + kp];                    al0[1] = sAl[rA + 8  * SA_STRIDE + kp];
        al0[2] = sAl[rA + kp + 4];                al0[3] = sAl[rA + 8  * SA_STRIDE + kp + 4];
        al1[0] = sAl[rA + 16 * SA_STRIDE + kp];   al1[1] = sAl[rA + 24 * SA_STRIDE + kp];
        al1[2] = sAl[rA + 16 * SA_STRIDE + kp+4]; al1[3] = sAl[rA + 24 * SA_STRIDE + kp + 4];

        const uint4* pb = pb0 + kt * 32;
        uint4 b[4];
        #pragma unroll
        for (int j = 0; j < 4; j++)
            b[j] = __ldg(pb + j * 256);

        #pragma unroll
        for (int j = 0; j < 4; j++) {
            mma_bf16(acc[0][j], ah0, b[j].x, b[j].y);
            mma_bf16(acc[1][j], ah1, b[j].x, b[j].y);
        }
        #pragma unroll
        for (int j = 0; j < 4; j++) {
            mma_bf16(acc[0][j], al0, b[j].x, b[j].y);
            mma_bf16(acc[1][j], al1, b[j].x, b[j].y);
        }
        #pragma unroll
        for (int j = 0; j < 4; j++) {
            mma_bf16(acc[0][j], ah0, b[j].z, b[j].w);
            mma_bf16(acc[1][j], ah1, b[j].z, b[j].w);
        }
    }

    #pragma unroll
    for (int m = 0; m < 2; m++) {
        int rr0 = row0 + wr * 32 + m * 16 + q;
        int rr1 = rr0 + 8;
        #pragma unroll
        for (int j = 0; j < 4; j++) {
            int col = (wc * 4 + j) * 8 + w * 2;
            if (rr0 < M)
                *(float2*)&C[(size_t)rr0 * DIM + col] = make_float2(acc[m][j][0], acc[m][j][1]);
            if (rr1 < M)
                *(float2*)&C[(size_t)rr1 * DIM + col] = make_float2(acc[m][j][2], acc[m][j][3]);
        }
    }
}

// ---------------- SpMM gather (R11 structure: 4-deep ILP + streaming store) -
template<bool LAYER1>
__global__ __launch_bounds__(256) void k_spmm(
    const float* __restrict__ feat, const int* __restrict__ x,
    const float* __restrict__ bias, float* __restrict__ out)
{
    int node = (int)((blockIdx.x * blockDim.x + threadIdx.x) >> 5);
    if (node >= NN) return;
    int lane = threadIdx.x & 31;

    int start = g_rowptr[node];
    int end   = g_rowptr[node + 1];
    const float4* f4 = (const float4*)feat;

    float ax = 0.f, ay = 0.f, az = 0.f, aw = 0.f;
    int k = start;
    for (; k + 3 < end; k += 4) {
        int c0 = g_col[k],     c1 = g_col[k + 1];
        int c2 = g_col[k + 2], c3 = g_col[k + 3];
        float w0 = g_dinv[c0], w1 = g_dinv[c1];
        float w2 = g_dinv[c2], w3 = g_dinv[c3];
        int r0 = LAYER1 ? x[c0] : c0;
        int r1 = LAYER1 ? x[c1] : c1;
        int r2 = LAYER1 ? x[c2] : c2;
        int r3 = LAYER1 ? x[c3] : c3;
        float4 v0 = f4[(size_t)r0 * 32 + lane];
        float4 v1 = f4[(size_t)r1 * 32 + lane];
        float4 v2 = f4[(size_t)r2 * 32 + lane];
        float4 v3 = f4[(size_t)r3 * 32 + lane];
        ax = fmaf(w0, v0.x, ax); ay = fmaf(w0, v0.y, ay);
        az = fmaf(w0, v0.z, az); aw = fmaf(w0, v0.w, aw);
        ax = fmaf(w1, v1.x, ax); ay = fmaf(w1, v1.y, ay);
        az = fmaf(w1, v1.z, az); aw = fmaf(w1, v1.w, aw);
        ax = fmaf(w2, v2.x, ax); ay = fmaf(w2, v2.y, ay);
        az = fmaf(w2, v2.z, az); aw = fmaf(w2, v2.w, aw);
        ax = fmaf(w3, v3.x, ax); ay = fmaf(w3, v3.y, ay);
        az = fmaf(w3, v3.z, az); aw = fmaf(w3, v3.w, aw);
    }
    for (; k < end; k++) {
        int c = g_col[k];
        float w = g_dinv[c];
        int r = LAYER1 ? x[c] : c;
        float4 v = f4[(size_t)r * 32 + lane];
        ax = fmaf(w, v.x, ax); ay = fmaf(w, v.y, ay);
        az = fmaf(w, v.z, az); aw = fmaf(w, v.w, aw);
    }

    float di = g_dinv[node];
    float4 b = __ldg((const float4*)bias + lane);
    float4 o;
    o.x = fmaxf(fmaf(di, ax, b.x), 0.f);
    o.y = fmaxf(fmaf(di, ay, b.y), 0.f);
    o.z = fmaxf(fmaf(di, az, b.z), 0.f);
    o.w = fmaxf(fmaf(di, aw, b.w), 0.f);
    __stcs((float4*)out + (size_t)node * 32 + lane, o);   // streaming store
}

// ---------------- launch ----------------------------------------------------
// Fork/join: CSR build (memory/atomic-bound) runs on a side stream overlapped
// with prep_wf+gemm1 (tensor-bound). Streams/events created per call (host
// objects; never destroyed to stay capture-legal). Join before spmm1.
extern "C" void kernel_launch(void* const* d_in, const int* in_sizes, int n_in,
                              void* d_out, int out_size) {
    const int*   x   = (const int*)d_in[0];
    const int*   src = (const int*)d_in[1];          // edge_index[0]
    const int*   dst = src + NE;                     // edge_index[1]
    const float* emb = (const float*)d_in[2];
    const float* W1  = (const float*)d_in[3];
    const float* b1  = (const float*)d_in[4];
    const float* W2  = (const float*)d_in[5];
    const float* b2  = (const float*)d_in[6];
    float*       out = (float*)d_out;

    float *p_embW, *p_agg, *p_hw;
    uint4 *p_Wf;
    int   *p_deg;
    cudaGetSymbolAddress((void**)&p_embW, g_embW);
    cudaGetSymbolAddress((void**)&p_agg,  g_agg);
    cudaGetSymbolAddress((void**)&p_hw,   g_hw);
    cudaGetSymbolAddress((void**)&p_Wf,   g_Wf);
    cudaGetSymbolAddress((void**)&p_deg,  g_deg);

    cudaFuncSetAttribute(k_gemm_mma, cudaFuncAttributeMaxDynamicSharedMemorySize, SMEM_GEMM);

    cudaStream_t s2;
    cudaEvent_t ev_fork, ev_join;
    cudaStreamCreateWithFlags(&s2, cudaStreamNonBlocking);
    cudaEventCreateWithFlags(&ev_fork, cudaEventDisableTiming);
    cudaEventCreateWithFlags(&ev_join, cudaEventDisableTiming);

    // fork: side stream joins the capture DAG
    cudaEventRecord(ev_fork, 0);
    cudaStreamWaitEvent(s2, ev_fork, 0);

    // Side stream: CSR chain (memset + 4 kernels)
    cudaMemsetAsync(p_deg, 0, NN * sizeof(int), s2);
    k_count_deg <<<(NE + 255) / 256, 256, 0, s2>>>(dst);             // kernel #1
    // Main stream: W prep + GEMM1 (independent of CSR)
    k_prep_wf   <<<(2 * 16 * 8 * 32 + 255) / 256, 256>>>(W1, W2);    // #2
    k_scan_fused<<<1, 1024, 0, s2>>>();                              // #3
    k_gemm_mma  <<<TILES1, 256, SMEM_GEMM>>>(emb, p_Wf, p_embW, NV); // #4 <- profiled
    k_fill_init <<<(NN + 255) / 256, 256, 0, s2>>>();                // #5
    k_fill_edges<<<(NE + 255) / 256, 256, 0, s2>>>(src, dst);        // #6

    // join: spmm1 needs both chains
    cudaEventRecord(ev_join, s2);
    cudaStreamWaitEvent(0, ev_join, 0);

    k_spmm<true><<<(NN + 7) / 8, 256>>>(p_embW, x, b1, p_agg);       // #7
    k_gemm_mma  <<<TILES2, 256, SMEM_GEMM>>>(p_agg, p_Wf + 16 * 8 * 32, p_hw, NN); // #8
    k_spmm<false><<<(NN + 7) / 8, 256>>>(p_hw, x, b2, out);          // #9
}